// round 11
// baseline (speedup 1.0000x reference)
#include <cuda_runtime.h>

#define FULL 0xffffffffu

// LISTA v7 = R9 body, ONE WARP PER SM.
// 64 blocks x 32 threads: block = warp = one batch column, so MIO queue /
// L1 / scheduler are warp-private (tests the shared-per-SM-contention
// hypothesis: six different bodies at 4 warps/SM all measured ~900cyc/stage).
// lane = h*16 + c*8 + i (h = j-half, c = re/im, i = position).
// Per-stage: 8 shfl broadcast -> 8 FMA half-dot (shared weight tables,
// sign pre-folded) -> shfl_xor reduce -> 4 shfl z-neighbors -> local conv1
// (3-op soft) -> conv2 (edge-zeroed weights, 3 accumulators).

__global__ void __launch_bounds__(32, 1) lista_kernel(
    const float* __restrict__ y_real, const float* __restrict__ y_imag,
    const float* __restrict__ w1_real, const float* __restrict__ w1_imag,
    const float* __restrict__ w2_real, const float* __restrict__ w2_imag,
    const float* __restrict__ thr,
    const float* __restrict__ c1w, const float* __restrict__ c1b,
    const float* __restrict__ c2w, const float* __restrict__ c2b,
    float* __restrict__ out)
{
    __shared__ __align__(16) float s_w2r [1024];   // w2_real, 16 stages
    __shared__ __align__(16) float s_w2ip[1024];   // +w2_imag (c=1)
    __shared__ __align__(16) float s_w2in[1024];   // -w2_imag (c=0)
    // packed conv params, 24 floats/stage:
    // [0..8]=k1, [9..11]=b1, [12..20]=k2, [21]=c2b, [22]=thr, [23]=pad
    __shared__ __align__(16) float s_cv[16 * 24];

    const int lane = threadIdx.x & 31;
    const int i    = lane & 7;
    const int c    = (lane >> 3) & 1;
    const int h    = lane >> 4;
    const int b    = (int)blockIdx.x;              // batch column (0..63)

    // ---- staging (single warp, strided by 32) ----
    {
        const float4* gr = (const float4*)w2_real;
        const float4* gi = (const float4*)w2_imag;
        #pragma unroll
        for (int k = lane; k < 256; k += 32) {
            float4 vr = gr[k];
            float4 vi = gi[k];
            ((float4*)s_w2r )[k] = vr;
            ((float4*)s_w2ip)[k] = vi;
            ((float4*)s_w2in)[k] = make_float4(-vi.x, -vi.y, -vi.z, -vi.w);
        }
    }
    #pragma unroll
    for (int k = lane; k < 384; k += 32) {
        int s = k / 24, r = k - s * 24;
        float v = 0.f;
        if (r < 9)        v = c1w[s * 9 + r];
        else if (r < 12)  v = c1b[s * 3 + (r - 9)];
        else if (r < 21)  v = c2w[s * 9 + (r - 12)];
        else if (r == 21) v = c2b[s];
        else if (r == 22) v = thr[s];
        s_cv[k] = v;
    }

    // ---- y half-slices (own comp + sign-folded opposite) ----
    const float sgn = c ? 1.f : -1.f;   // z_r: -wi*x_i ; z_i: +wi*x_r
    float yc[4], yos[4];
    {
        const float* yc_ptr = c ? y_imag : y_real;
        const float* yo_ptr = c ? y_real : y_imag;
        #pragma unroll
        for (int j4 = 0; j4 < 4; j4++) {
            int j = h * 4 + j4;
            yc[j4]  = yc_ptr[j * 64 + b];
            yos[j4] = sgn * yo_ptr[j * 64 + b];
        }
    }

    // ---- precompute 16 stage HALF-biases (W1[s] y), this j-half ----
    float bias[16];
    #pragma unroll
    for (int s = 0; s < 16; s++) {
        const float4 wr = *(const float4*)(w1_real + s * 64 + i * 8 + h * 4);
        const float4 wi = *(const float4*)(w1_imag + s * 64 + i * 8 + h * 4);
        float a0 = 0.f, a1 = 0.f;
        a0 = fmaf(wr.x, yc[0], a0); a1 = fmaf(wi.x, yos[0], a1);
        a0 = fmaf(wr.y, yc[1], a0); a1 = fmaf(wi.y, yos[1], a1);
        a0 = fmaf(wr.z, yc[2], a0); a1 = fmaf(wi.z, yos[2], a1);
        a0 = fmaf(wr.w, yc[3], a0); a1 = fmaf(wi.w, yos[3], a1);
        bias[s] = a0 + a1;
    }

    __syncwarp();   // single-warp block: warp sync suffices for smem staging

    // ---- static pointers (loop body: LDS [ptr + imm] only) ----
    const float* pw_r = s_w2r + i * 8 + h * 4;
    const float* pw_i = (c ? s_w2ip : s_w2in) + i * 8 + h * 4;
    const bool   e0 = (i > 0), e2 = (i < 7);

    // ---- init: x = soft(full bias[0], thr[0]) ----
    float x;
    {
        const float b0 = bias[0] + __shfl_xor_sync(FULL, bias[0], 16);
        const float t0 = s_cv[22];
        x = b0 - fminf(fmaxf(b0, -t0), t0);
    }

    const int src_c = (c << 3);        // lanes holding own-comp x_j
    const int src_o = ((c ^ 1) << 3);  // lanes holding opposite-comp x_j
    const int nbase = lane & 24;       // keep (c,h) bits for neighbor shfl

    // ---- 16 sequential stages (fully unrolled) ----
    #pragma unroll
    for (int s = 0; s < 16; s++) {
        // broadcast x for this thread's j-half
        float xc[4], xo[4];
        #pragma unroll
        for (int j4 = 0; j4 < 4; j4++) {
            int j = h * 4 + j4;
            xc[j4] = __shfl_sync(FULL, x, src_c + j);
            xo[j4] = __shfl_sync(FULL, x, src_o + j);
        }

        // half dot from shared weight tables
        const float4 wr = *(const float4*)(pw_r + s * 64);
        const float4 wi = *(const float4*)(pw_i + s * 64);
        float a0 = bias[s], a1 = 0.f;
        a0 = fmaf(wr.x, xc[0], a0); a1 = fmaf(wi.x, xo[0], a1);
        a0 = fmaf(wr.y, xc[1], a0); a1 = fmaf(wi.y, xo[1], a1);
        a0 = fmaf(wr.z, xc[2], a0); a1 = fmaf(wi.z, xo[2], a1);
        a0 = fmaf(wr.w, xc[3], a0); a1 = fmaf(wi.w, xo[3], a1);
        const float a = a0 + a1;
        const float z = a + __shfl_xor_sync(FULL, a, 16);  // full bias+dot

        // z neighbors at +-1,+-2 (same component, zero-padded via SEL)
        float zv[5];
        zv[2] = z;
        float zm2 = __shfl_sync(FULL, z, nbase | ((i - 2) & 7));
        float zm1 = __shfl_sync(FULL, z, nbase | ((i - 1) & 7));
        float zp1 = __shfl_sync(FULL, z, nbase | ((i + 1) & 7));
        float zp2 = __shfl_sync(FULL, z, nbase | ((i + 2) & 7));
        zv[0] = (i >= 2) ? zm2 : 0.f;
        zv[1] = (i >= 1) ? zm1 : 0.f;
        zv[3] = (i <= 6) ? zp1 : 0.f;
        zv[4] = (i <= 5) ? zp2 : 0.f;

        // packed conv params: 6 broadcast LDS.128
        const float4 q0 = *(const float4*)(s_cv + s * 24);
        const float4 q1 = *(const float4*)(s_cv + s * 24 + 4);
        const float4 q2 = *(const float4*)(s_cv + s * 24 + 8);
        const float4 q3 = *(const float4*)(s_cv + s * 24 + 12);
        const float4 q4 = *(const float4*)(s_cv + s * 24 + 16);
        const float4 q5 = *(const float4*)(s_cv + s * 24 + 20);
        const float k1[3][3] = {{q0.x, q0.y, q0.z},
                                {q0.w, q1.x, q1.y},
                                {q1.z, q1.w, q2.x}};
        const float bb1[3] = {q2.y, q2.z, q2.w};
        // k2 row-major with edge taps zeroed OFF the z-dependent chain
        const float k2m[3][3] = {{e0 ? q3.x : 0.f, q3.y, e2 ? q3.z : 0.f},
                                 {e0 ? q3.w : 0.f, q4.x, e2 ? q4.y : 0.f},
                                 {e0 ? q4.z : 0.f, q4.w, e2 ? q5.x : 0.f}};
        const float cb2 = q5.y;
        const float t   = q5.z;
        const float tn  = -t;

        // conv1 + 3-op soft at pos i-1, i, i+1; conv2 with 3 accumulators
        float o0 = cb2, o1 = 0.f, o2 = 0.f;
        #pragma unroll
        for (int ch = 0; ch < 3; ch++) {
            const float w0 = k1[ch][0], w1 = k1[ch][1], w2 = k1[ch][2];
            const float bb = bb1[ch];
            float v0 = bb, v1 = bb, v2 = bb;
            v0 = fmaf(w0, zv[0], v0); v1 = fmaf(w0, zv[1], v1); v2 = fmaf(w0, zv[2], v2);
            v0 = fmaf(w1, zv[1], v0); v1 = fmaf(w1, zv[2], v1); v2 = fmaf(w1, zv[3], v2);
            v0 = fmaf(w2, zv[2], v0); v1 = fmaf(w2, zv[3], v1); v2 = fmaf(w2, zv[4], v2);
            const float s0 = v0 - fminf(fmaxf(v0, tn), t);
            const float s1 = v1 - fminf(fmaxf(v1, tn), t);
            const float s2 = v2 - fminf(fmaxf(v2, tn), t);
            o0 = fmaf(k2m[ch][0], s0, o0);
            o1 = fmaf(k2m[ch][1], s1, o1);
            o2 = fmaf(k2m[ch][2], s2, o2);
        }
        x = (o0 + o1) + o2;
    }

    // out: x_r (8,64) then x_i (8,64); h=0 lanes write
    if (h == 0) out[c * 512 + i * 64 + b] = x;
}

extern "C" void kernel_launch(void* const* d_in, const int* in_sizes, int n_in,
                              void* d_out, int out_size) {
    (void)in_sizes; (void)n_in; (void)out_size;
    const float* y_real  = (const float*)d_in[0];
    const float* y_imag  = (const float*)d_in[1];
    const float* w1_real = (const float*)d_in[2];
    const float* w1_imag = (const float*)d_in[3];
    const float* w2_real = (const float*)d_in[4];
    const float* w2_imag = (const float*)d_in[5];
    const float* thr     = (const float*)d_in[6];
    const float* c1w     = (const float*)d_in[7];
    const float* c1b     = (const float*)d_in[8];
    const float* c2w     = (const float*)d_in[9];
    const float* c2b     = (const float*)d_in[10];
    float* out = (float*)d_out;

    // one warp per SM: block = warp = one batch column
    lista_kernel<<<64, 32>>>(y_real, y_imag, w1_real, w1_imag,
                             w2_real, w2_imag, thr, c1w, c1b, c2w, c2b, out);
}

// round 12
// speedup vs baseline: 1.1910x; 1.1910x over previous
#include <cuda_runtime.h>

#define FULL 0xffffffffu

// LISTA v8 = R9 base + (1) bias pipelined INTO the stage loop (prolog work
// hidden in per-stage stall windows) + (2) merged reduce+neighbor shuffle
// waves: fetch half-dot partials a(h,pos) for pos=i-2..i+2 in ONE wave and
// sum locally (z never materialized via a separate reduce wave).
// lane = h*16 + c*8 + i; warp = one column; 16 blocks x 128 threads.

__global__ void __launch_bounds__(128, 1) lista_kernel(
    const float* __restrict__ y_real, const float* __restrict__ y_imag,
    const float* __restrict__ w1_real, const float* __restrict__ w1_imag,
    const float* __restrict__ w2_real, const float* __restrict__ w2_imag,
    const float* __restrict__ thr,
    const float* __restrict__ c1w, const float* __restrict__ c1b,
    const float* __restrict__ c2w, const float* __restrict__ c2b,
    float* __restrict__ out)
{
    __shared__ __align__(16) float s_w2r [1024];   // w2_real, 16 stages
    __shared__ __align__(16) float s_w2ip[1024];   // +w2_imag (c=1)
    __shared__ __align__(16) float s_w2in[1024];   // -w2_imag (c=0)
    // packed conv params, 24 floats/stage:
    // [0..8]=k1, [9..11]=b1, [12..20]=k2, [21]=c2b, [22]=thr, [23]=pad
    __shared__ __align__(16) float s_cv[16 * 24];

    const int tid  = threadIdx.x;          // 0..127
    const int lane = tid & 31;
    const int i    = lane & 7;
    const int c    = (lane >> 3) & 1;
    const int h    = lane >> 4;
    const int b    = (int)blockIdx.x * 4 + (tid >> 5);   // batch column

    // ---- staging: W2 tables (+/- imag), packed conv params ----
    {
        const float4* gr = (const float4*)w2_real;
        const float4* gi = (const float4*)w2_imag;
        #pragma unroll
        for (int k = tid; k < 256; k += 128) {
            float4 vr = gr[k];
            float4 vi = gi[k];
            ((float4*)s_w2r )[k] = vr;
            ((float4*)s_w2ip)[k] = vi;
            ((float4*)s_w2in)[k] = make_float4(-vi.x, -vi.y, -vi.z, -vi.w);
        }
    }
    #pragma unroll
    for (int k = tid; k < 384; k += 128) {
        int s = k / 24, r = k - s * 24;
        float v = 0.f;
        if (r < 9)        v = c1w[s * 9 + r];
        else if (r < 12)  v = c1b[s * 3 + (r - 9)];
        else if (r < 21)  v = c2w[s * 9 + (r - 12)];
        else if (r == 21) v = c2b[s];
        else if (r == 22) v = thr[s];
        s_cv[k] = v;
    }

    // ---- y half-slices (own comp + sign-folded opposite) ----
    const float sgn = c ? 1.f : -1.f;   // z_r: -wi*x_i ; z_i: +wi*x_r
    float yc[4], yos[4];
    {
        const float* yc_ptr = c ? y_imag : y_real;
        const float* yo_ptr = c ? y_real : y_imag;
        #pragma unroll
        for (int j4 = 0; j4 < 4; j4++) {
            int j = h * 4 + j4;
            yc[j4]  = yc_ptr[j * 64 + b];
            yos[j4] = sgn * yo_ptr[j * 64 + b];
        }
    }

    // half-bias helper: (W1[s] y), this thread's j-half
    const float* w1r_base = w1_real + i * 8 + h * 4;
    const float* w1i_base = w1_imag + i * 8 + h * 4;
    #define HALF_BIAS(dst, s_)                                             \
    {                                                                       \
        const float4 wr = *(const float4*)(w1r_base + (s_) * 64);          \
        const float4 wi = *(const float4*)(w1i_base + (s_) * 64);          \
        float a0_ = 0.f, a1_ = 0.f;                                         \
        a0_ = fmaf(wr.x, yc[0], a0_); a1_ = fmaf(wi.x, yos[0], a1_);       \
        a0_ = fmaf(wr.y, yc[1], a0_); a1_ = fmaf(wi.y, yos[1], a1_);       \
        a0_ = fmaf(wr.z, yc[2], a0_); a1_ = fmaf(wi.z, yos[2], a1_);       \
        a0_ = fmaf(wr.w, yc[3], a0_); a1_ = fmaf(wi.w, yos[3], a1_);       \
        dst = a0_ + a1_;                                                    \
    }

    // only stage-0 bias in the prolog; the rest pipeline into the loop
    float hb_cur;
    HALF_BIAS(hb_cur, 0);

    __syncthreads();

    // ---- static pointers ----
    const float* pw_r = s_w2r + i * 8 + h * 4;
    const float* pw_i = (c ? s_w2ip : s_w2in) + i * 8 + h * 4;
    const bool   e0 = (i > 0), e2 = (i < 7);

    // ---- init: x = soft(full bias[0], thr[0]) ----
    float x;
    {
        const float b0 = hb_cur + __shfl_xor_sync(FULL, hb_cur, 16);
        const float t0 = s_cv[22];
        x = b0 - fminf(fmaxf(b0, -t0), t0);
    }

    const int src_c = (c << 3);        // lanes (h=0) holding own-comp x_j
    const int src_o = ((c ^ 1) << 3);  // opposite comp
    const int pc    = c << 3;          // partial-fetch base (own comp)

    // ---- 16 sequential stages (fully unrolled) ----
    #pragma unroll
    for (int s = 0; s < 16; s++) {
        // pipelined half-bias for NEXT stage (x-independent; hides in
        // this stage's stall windows — LDG has a full stage to land)
        float hb_nxt = 0.f;
        if (s < 15) HALF_BIAS(hb_nxt, s + 1);

        // wave 1: broadcast x for this thread's j-half
        float xc[4], xo[4];
        #pragma unroll
        for (int j4 = 0; j4 < 4; j4++) {
            int j = h * 4 + j4;
            xc[j4] = __shfl_sync(FULL, x, src_c + j);
            xo[j4] = __shfl_sync(FULL, x, src_o + j);
        }

        // half dot (weights from shared, sign pre-folded)
        const float4 wr = *(const float4*)(pw_r + s * 64);
        const float4 wi = *(const float4*)(pw_i + s * 64);
        float a0 = hb_cur, a1 = 0.f;
        a0 = fmaf(wr.x, xc[0], a0); a1 = fmaf(wi.x, xo[0], a1);
        a0 = fmaf(wr.y, xc[1], a0); a1 = fmaf(wi.y, xo[1], a1);
        a0 = fmaf(wr.z, xc[2], a0); a1 = fmaf(wi.z, xo[2], a1);
        a0 = fmaf(wr.w, xc[3], a0); a1 = fmaf(wi.w, xo[3], a1);
        const float a = a0 + a1;

        // wave 2 (merged reduce + neighbors): fetch BOTH half partials of
        // a at positions i-2..i+2 and sum locally. One dependent wave.
        const int pm2 = pc | ((i - 2) & 7), pm1 = pc | ((i - 1) & 7);
        const int pp1 = pc | ((i + 1) & 7), pp2 = pc | ((i + 2) & 7);
        const float q0a = __shfl_sync(FULL, a, pm2);
        const float q0b = __shfl_sync(FULL, a, 16 | pm2);
        const float q1a = __shfl_sync(FULL, a, pm1);
        const float q1b = __shfl_sync(FULL, a, 16 | pm1);
        const float q2a = __shfl_sync(FULL, a, pc | i);
        const float q2b = __shfl_sync(FULL, a, 16 | pc | i);
        const float q3a = __shfl_sync(FULL, a, pp1);
        const float q3b = __shfl_sync(FULL, a, 16 | pp1);
        const float q4a = __shfl_sync(FULL, a, pp2);
        const float q4b = __shfl_sync(FULL, a, 16 | pp2);
        float zv[5];
        zv[0] = (i >= 2) ? (q0a + q0b) : 0.f;
        zv[1] = (i >= 1) ? (q1a + q1b) : 0.f;
        zv[2] = q2a + q2b;
        zv[3] = (i <= 6) ? (q3a + q3b) : 0.f;
        zv[4] = (i <= 5) ? (q4a + q4b) : 0.f;

        // packed conv params: 6 broadcast LDS.128 (hoistable)
        const float4 c0 = *(const float4*)(s_cv + s * 24);
        const float4 c1 = *(const float4*)(s_cv + s * 24 + 4);
        const float4 c2v = *(const float4*)(s_cv + s * 24 + 8);
        const float4 c3 = *(const float4*)(s_cv + s * 24 + 12);
        const float4 c4 = *(const float4*)(s_cv + s * 24 + 16);
        const float4 c5 = *(const float4*)(s_cv + s * 24 + 20);
        const float k1[3][3] = {{c0.x, c0.y, c0.z},
                                {c0.w, c1.x, c1.y},
                                {c1.z, c1.w, c2v.x}};
        const float bb1[3] = {c2v.y, c2v.z, c2v.w};
        const float k2m[3][3] = {{e0 ? c3.x : 0.f, c3.y, e2 ? c3.z : 0.f},
                                 {e0 ? c3.w : 0.f, c4.x, e2 ? c4.y : 0.f},
                                 {e0 ? c4.z : 0.f, c4.w, e2 ? c5.x : 0.f}};
        const float cb2 = c5.y;
        const float t   = c5.z;
        const float tn  = -t;

        // conv1 + 3-op soft at pos i-1, i, i+1; conv2 with 3 accumulators
        float o0 = cb2, o1 = 0.f, o2 = 0.f;
        #pragma unroll
        for (int ch = 0; ch < 3; ch++) {
            const float w0 = k1[ch][0], w1 = k1[ch][1], w2 = k1[ch][2];
            const float bb = bb1[ch];
            float v0 = bb, v1 = bb, v2 = bb;
            v0 = fmaf(w0, zv[0], v0); v1 = fmaf(w0, zv[1], v1); v2 = fmaf(w0, zv[2], v2);
            v0 = fmaf(w1, zv[1], v0); v1 = fmaf(w1, zv[2], v1); v2 = fmaf(w1, zv[3], v2);
            v0 = fmaf(w2, zv[2], v0); v1 = fmaf(w2, zv[3], v1); v2 = fmaf(w2, zv[4], v2);
            const float s0 = v0 - fminf(fmaxf(v0, tn), t);
            const float s1 = v1 - fminf(fmaxf(v1, tn), t);
            const float s2 = v2 - fminf(fmaxf(v2, tn), t);
            o0 = fmaf(k2m[ch][0], s0, o0);
            o1 = fmaf(k2m[ch][1], s1, o1);
            o2 = fmaf(k2m[ch][2], s2, o2);
        }
        x = (o0 + o1) + o2;
        hb_cur = hb_nxt;
    }
    #undef HALF_BIAS

    // out: x_r (8,64) then x_i (8,64); h=0 lanes write
    if (h == 0) out[c * 512 + i * 64 + b] = x;
}

extern "C" void kernel_launch(void* const* d_in, const int* in_sizes, int n_in,
                              void* d_out, int out_size) {
    (void)in_sizes; (void)n_in; (void)out_size;
    const float* y_real  = (const float*)d_in[0];
    const float* y_imag  = (const float*)d_in[1];
    const float* w1_real = (const float*)d_in[2];
    const float* w1_imag = (const float*)d_in[3];
    const float* w2_real = (const float*)d_in[4];
    const float* w2_imag = (const float*)d_in[5];
    const float* thr     = (const float*)d_in[6];
    const float* c1w     = (const float*)d_in[7];
    const float* c1b     = (const float*)d_in[8];
    const float* c2w     = (const float*)d_in[9];
    const float* c2b     = (const float*)d_in[10];
    float* out = (float*)d_out;

    lista_kernel<<<16, 128>>>(y_real, y_imag, w1_real, w1_imag,
                              w2_real, w2_imag, thr, c1w, c1b, c2w, c2b, out);
}